// round 7
// baseline (speedup 1.0000x reference)
#include <cuda_runtime.h>
#include <math.h>

// Problem constants (fixed by the reference's setup)
#define N_IN 1000000
#define M_NODES 2000000
#define S0 (2 * N_IN + 2)
#define HALF_M (M_NODES / 2)   // 1,000,000: each thread handles m and m+HALF_M

// Scratch (no cudaMalloc allowed): encoded input + two ping-pong M-buffers
__device__ float g_enc[S0];
__device__ float g_bufA[M_NODES];
__device__ float g_bufB[M_NODES];

// log(1 - exp(x)) for x <= 0, stable (Maechler 2012), matching reference
__device__ __forceinline__ float log1mexp_f(float x) {
    const float NLOG2 = -0.69314718056f;
    if (x > NLOG2) {
        return logf(-expm1f(x));     // x in (-log2, 0]; x=0 -> log(0) = -inf
    } else {
        return log1pf(-expf(x));
    }
}

__global__ void __launch_bounds__(256) encode_kernel(const float* __restrict__ pos) {
    int i = blockIdx.x * blockDim.x + threadIdx.x;
    if (i == 0) {
        g_enc[0] = -INFINITY;  // literal False
        g_enc[1] = 0.0f;       // literal True
    }
    if (i < N_IN) {
        float p = pos[i];
        g_enc[2 + 2 * i] = p;
        g_enc[3 + 2 * i] = log1mexp_f(p);
    }
}

// Gather with L1-bypass: random 4B gathers have ~3% L1 hit rate; skip the fill.
__device__ __forceinline__ float gcg(const float* p) { return __ldcg(p); }

// product layer: out[m] = sum of 4 gathered log-probs.
// ILP=2 via grid-split: thread t handles nodes t and t+HALF_M. Both ptr
// loads coalesced & issued together; 8 gathers in flight concurrently.
__global__ void __launch_bounds__(256) product_kernel(
        const float* __restrict__ src,
        const int4* __restrict__ ptrs,
        float* __restrict__ dst) {
    int t = blockIdx.x * blockDim.x + threadIdx.x;
    if (t >= HALF_M) return;
    int4 p0 = __ldcs(ptrs + t);
    int4 p1 = __ldcs(ptrs + t + HALF_M);

    float a0 = gcg(src + p0.x), b0 = gcg(src + p0.y);
    float c0 = gcg(src + p0.z), d0 = gcg(src + p0.w);
    float a1 = gcg(src + p1.x), b1 = gcg(src + p1.y);
    float c1 = gcg(src + p1.z), d1 = gcg(src + p1.w);

    __stcg(dst + t,          (a0 + b0) + (c0 + d0));
    __stcg(dst + t + HALF_M, (a1 + b1) + (c1 + d1));
}

// 4-way logsumexp with 1e-15 floor, max detached (reference nan_to_num path
// makes an all -inf group yield -inf).
__device__ __forceinline__ float lse4(float a, float b, float c, float d) {
    float mx = fmaxf(fmaxf(a, b), fmaxf(c, d));
    if (mx == -INFINITY) return -INFINITY;
    float s = __expf(a - mx) + __expf(b - mx) + __expf(c - mx) + __expf(d - mx);
    return __logf(s + 1e-15f) + mx;
}

__global__ void __launch_bounds__(256) sum_kernel(
        const float* __restrict__ src,
        const int4* __restrict__ ptrs,
        float* __restrict__ dst) {
    int t = blockIdx.x * blockDim.x + threadIdx.x;
    if (t >= HALF_M) return;
    int4 p0 = __ldcs(ptrs + t);
    int4 p1 = __ldcs(ptrs + t + HALF_M);

    float a0 = gcg(src + p0.x), b0 = gcg(src + p0.y);
    float c0 = gcg(src + p0.z), d0 = gcg(src + p0.w);
    float a1 = gcg(src + p1.x), b1 = gcg(src + p1.y);
    float c1 = gcg(src + p1.z), d1 = gcg(src + p1.w);

    __stcg(dst + t,          lse4(a0, b0, c0, d0));
    __stcg(dst + t + HALF_M, lse4(a1, b1, c1, d1));
}

extern "C" void kernel_launch(void* const* d_in, const int* in_sizes, int n_in,
                              void* d_out, int out_size) {
    const float* pos   = (const float*)d_in[0];
    const int4*  ptrs0 = (const int4*)d_in[1];
    const int4*  ptrs1 = (const int4*)d_in[2];
    const int4*  ptrs2 = (const int4*)d_in[3];
    const int4*  ptrs3 = (const int4*)d_in[4];
    // d_in[5] (csr = repeat(arange(M),4)) is implicit in the layout.
    float* out = (float*)d_out;

    float* enc;  cudaGetSymbolAddress((void**)&enc,  g_enc);
    float* bufA; cudaGetSymbolAddress((void**)&bufA, g_bufA);
    float* bufB; cudaGetSymbolAddress((void**)&bufB, g_bufB);

    const int T = 256;
    const int blocksEnc = (N_IN + T - 1) / T;
    const int blocksM   = (HALF_M + T - 1) / T;   // 3907 blocks, multi-wave

    encode_kernel <<<blocksEnc, T>>>(pos);
    product_kernel<<<blocksM, T>>>(enc,  ptrs0, bufA);
    sum_kernel    <<<blocksM, T>>>(bufA, ptrs1, bufB);
    product_kernel<<<blocksM, T>>>(bufB, ptrs2, bufA);
    sum_kernel    <<<blocksM, T>>>(bufA, ptrs3, out);
}

// round 8
// speedup vs baseline: 1.4807x; 1.4807x over previous
#include <cuda_runtime.h>
#include <math.h>

// Problem constants (fixed by the reference's setup)
#define N_IN 1000000
#define M_NODES 2000000
#define S0 (2 * N_IN + 2)

// Scratch (no cudaMalloc allowed): encoded input + two ping-pong M-buffers
__device__ float g_enc[S0];
__device__ float g_bufA[M_NODES];
__device__ float g_bufB[M_NODES];

// log(1 - exp(x)) for x <= 0, stable (Maechler 2012), matching reference
__device__ __forceinline__ float log1mexp_f(float x) {
    const float NLOG2 = -0.69314718056f;
    if (x > NLOG2) {
        return logf(-expm1f(x));     // x in (-log2, 0]; x=0 -> log(0) = -inf
    } else {
        return log1pf(-expf(x));
    }
}

__global__ void __launch_bounds__(512) encode_kernel(const float* __restrict__ pos) {
    int i = blockIdx.x * blockDim.x + threadIdx.x;
    if (i == 0) {
        g_enc[0] = -INFINITY;  // literal False
        g_enc[1] = 0.0f;       // literal True
    }
    if (i < N_IN) {
        float p = pos[i];
        g_enc[2 + 2 * i] = p;
        g_enc[3 + 2 * i] = log1mexp_f(p);
    }
}

// Gather with L1-bypass: random 4B gathers have ~3% L1 hit rate; skip the fill.
__device__ __forceinline__ float gcg(const float* p) { return __ldcg(p); }

// product layer: flat ILP=1, best measured shape (34.2 us).
__global__ void __launch_bounds__(256) product_kernel(
        const float* __restrict__ src,
        const int4* __restrict__ ptrs,
        float* __restrict__ dst) {
    int m = blockIdx.x * blockDim.x + threadIdx.x;
    if (m >= M_NODES) return;
    int4 p = __ldcs(ptrs + m);          // streaming: touch-once pointer data
    float a = gcg(src + p.x);
    float b = gcg(src + p.y);
    float c = gcg(src + p.z);
    float d = gcg(src + p.w);
    __stcg(dst + m, (a + b) + (c + d)); // output re-read only via L2 gathers
}

// sum layer: persistent grid-stride with 2-stage ptr pipeline, best measured
// shape (~29.7 us): the prefetched next-ptr DRAM load overlaps the MUFU
// (exp/log) work of the current iteration.
__global__ void __launch_bounds__(512) sum_kernel(
        const float* __restrict__ src,
        const int4* __restrict__ ptrs,
        float* __restrict__ dst) {
    const int stride = gridDim.x * blockDim.x;
    int m = blockIdx.x * blockDim.x + threadIdx.x;
    if (m >= M_NODES) return;
    int4 p = __ldcs(ptrs + m);
    while (true) {
        int mn = m + stride;
        int4 pn;
        if (mn < M_NODES) pn = __ldcs(ptrs + mn);   // prefetch next ptrs
        float a = gcg(src + p.x);
        float b = gcg(src + p.y);
        float c = gcg(src + p.z);
        float d = gcg(src + p.w);
        float mx = fmaxf(fmaxf(a, b), fmaxf(c, d));
        float out;
        if (mx == -INFINITY) {
            out = -INFINITY;            // reference nan_to_num path
        } else {
            float s = __expf(a - mx) + __expf(b - mx)
                    + __expf(c - mx) + __expf(d - mx);
            out = __logf(s + 1e-15f) + mx;
        }
        __stcg(dst + m, out);
        if (mn >= M_NODES) break;
        m = mn; p = pn;
    }
}

extern "C" void kernel_launch(void* const* d_in, const int* in_sizes, int n_in,
                              void* d_out, int out_size) {
    const float* pos   = (const float*)d_in[0];
    const int4*  ptrs0 = (const int4*)d_in[1];
    const int4*  ptrs1 = (const int4*)d_in[2];
    const int4*  ptrs2 = (const int4*)d_in[3];
    const int4*  ptrs3 = (const int4*)d_in[4];
    // d_in[5] (csr = repeat(arange(M),4)) is implicit in the layout.
    float* out = (float*)d_out;

    float* enc;  cudaGetSymbolAddress((void**)&enc,  g_enc);
    float* bufA; cudaGetSymbolAddress((void**)&bufA, g_bufA);
    float* bufB; cudaGetSymbolAddress((void**)&bufB, g_bufB);

    const int TP = 256;                               // product/encode blocks
    const int blocksEnc = (N_IN + 511) / 512;
    const int blocksP   = (M_NODES + TP - 1) / TP;    // flat multi-wave
    const int TS = 512;
    const int blocksS   = 148 * 4;                    // persistent, one wave

    encode_kernel <<<blocksEnc, 512>>>(pos);
    product_kernel<<<blocksP, TP>>>(enc,  ptrs0, bufA);
    sum_kernel    <<<blocksS, TS>>>(bufA, ptrs1, bufB);
    product_kernel<<<blocksP, TP>>>(bufB, ptrs2, bufA);
    sum_kernel    <<<blocksS, TS>>>(bufA, ptrs3, out);
}

// round 9
// speedup vs baseline: 1.5690x; 1.0596x over previous
#include <cuda_runtime.h>
#include <math.h>

// Problem constants (fixed by the reference's setup)
#define N_IN 1000000
#define M_NODES 2000000
#define S0 (2 * N_IN + 2)

// Scratch (no cudaMalloc allowed): encoded input + two ping-pong M-buffers
__device__ float g_enc[S0];
__device__ float g_bufA[M_NODES];
__device__ float g_bufB[M_NODES];

// log(1 - exp(x)) for x <= 0, stable (Maechler 2012), matching reference
__device__ __forceinline__ float log1mexp_f(float x) {
    const float NLOG2 = -0.69314718056f;
    if (x > NLOG2) {
        return logf(-expm1f(x));     // x in (-log2, 0]; x=0 -> log(0) = -inf
    } else {
        return log1pf(-expf(x));
    }
}

__global__ void __launch_bounds__(512) encode_kernel(const float* __restrict__ pos) {
    int i = blockIdx.x * blockDim.x + threadIdx.x;
    if (i == 0) {
        g_enc[0] = -INFINITY;  // literal False
        g_enc[1] = 0.0f;       // literal True
    }
    if (i < N_IN) {
        float p = pos[i];
        g_enc[2 + 2 * i] = p;
        g_enc[3 + 2 * i] = log1mexp_f(p);
    }
}

// Gather with L1-bypass: random 4B gathers have ~3% L1 hit rate; skip the fill.
__device__ __forceinline__ float gcg(const float* p) { return __ldcg(p); }

// product layer: out[m] = sum of 4 gathered log-probs.
// Grid-stride, 2-stage software pipeline: next iteration's ptr int4 is in
// flight (DRAM) while this iteration's gathers (L2) are serviced.
__global__ void __launch_bounds__(512) product_kernel(
        const float* __restrict__ src,
        const int4* __restrict__ ptrs,
        float* __restrict__ dst) {
    const int stride = gridDim.x * blockDim.x;
    int m = blockIdx.x * blockDim.x + threadIdx.x;
    if (m >= M_NODES) return;
    int4 p = __ldcs(ptrs + m);
    while (true) {
        int mn = m + stride;
        int4 pn;
        if (mn < M_NODES) pn = __ldcs(ptrs + mn);   // prefetch next ptrs
        float a = gcg(src + p.x);
        float b = gcg(src + p.y);
        float c = gcg(src + p.z);
        float d = gcg(src + p.w);
        __stcg(dst + m, (a + b) + (c + d));
        if (mn >= M_NODES) break;
        m = mn; p = pn;
    }
}

// sum layer: 4-way logsumexp with 1e-15 floor, max detached. Same pipeline.
__global__ void __launch_bounds__(512) sum_kernel(
        const float* __restrict__ src,
        const int4* __restrict__ ptrs,
        float* __restrict__ dst) {
    const int stride = gridDim.x * blockDim.x;
    int m = blockIdx.x * blockDim.x + threadIdx.x;
    if (m >= M_NODES) return;
    int4 p = __ldcs(ptrs + m);
    while (true) {
        int mn = m + stride;
        int4 pn;
        if (mn < M_NODES) pn = __ldcs(ptrs + mn);
        float a = gcg(src + p.x);
        float b = gcg(src + p.y);
        float c = gcg(src + p.z);
        float d = gcg(src + p.w);
        float mx = fmaxf(fmaxf(a, b), fmaxf(c, d));
        float out;
        if (mx == -INFINITY) {
            out = -INFINITY;            // reference nan_to_num path
        } else {
            float s = __expf(a - mx) + __expf(b - mx)
                    + __expf(c - mx) + __expf(d - mx);
            out = __logf(s + 1e-15f) + mx;
        }
        __stcg(dst + m, out);
        if (mn >= M_NODES) break;
        m = mn; p = pn;
    }
}

extern "C" void kernel_launch(void* const* d_in, const int* in_sizes, int n_in,
                              void* d_out, int out_size) {
    const float* pos   = (const float*)d_in[0];
    const int4*  ptrs0 = (const int4*)d_in[1];
    const int4*  ptrs1 = (const int4*)d_in[2];
    const int4*  ptrs2 = (const int4*)d_in[3];
    const int4*  ptrs3 = (const int4*)d_in[4];
    // d_in[5] (csr = repeat(arange(M),4)) is implicit in the layout.
    float* out = (float*)d_out;

    float* enc;  cudaGetSymbolAddress((void**)&enc,  g_enc);
    float* bufA; cudaGetSymbolAddress((void**)&bufA, g_bufA);
    float* bufB; cudaGetSymbolAddress((void**)&bufB, g_bufB);

    const int T = 512;
    const int blocksEnc = (N_IN + T - 1) / T;
    const int blocksM   = 148 * 4;   // 4 blocks/SM resident; grid-stride covers M

    encode_kernel <<<blocksEnc, T>>>(pos);
    product_kernel<<<blocksM, T>>>(enc,  ptrs0, bufA);
    sum_kernel    <<<blocksM, T>>>(bufA, ptrs1, bufB);
    product_kernel<<<blocksM, T>>>(bufB, ptrs2, bufA);
    sum_kernel    <<<blocksM, T>>>(bufA, ptrs3, out);
}

// round 10
// speedup vs baseline: 1.5834x; 1.0092x over previous
#include <cuda_runtime.h>
#include <math.h>

// Problem constants (fixed by the reference's setup)
#define N_IN 1000000
#define M_NODES 2000000
#define S0 (2 * N_IN + 2)

// Scratch (no cudaMalloc allowed): encoded input + two ping-pong M-buffers
__device__ float g_enc[S0];
__device__ float g_bufA[M_NODES];
__device__ float g_bufB[M_NODES];

// log(1 - exp(x)) for x <= 0, stable (Maechler 2012), matching reference
__device__ __forceinline__ float log1mexp_f(float x) {
    const float NLOG2 = -0.69314718056f;
    if (x > NLOG2) {
        return logf(-expm1f(x));     // x in (-log2, 0]; x=0 -> log(0) = -inf
    } else {
        return log1pf(-expf(x));
    }
}

__global__ void __launch_bounds__(512) encode_kernel(const float* __restrict__ pos) {
    int i = blockIdx.x * blockDim.x + threadIdx.x;
    if (i == 0) {
        g_enc[0] = -INFINITY;  // literal False
        g_enc[1] = 0.0f;       // literal True
    }
    if (i < N_IN) {
        float p = pos[i];
        g_enc[2 + 2 * i] = p;
        g_enc[3 + 2 * i] = log1mexp_f(p);
    }
}

// Gather with L1-bypass: random 4B gathers have ~3% L1 hit rate; skip the fill.
__device__ __forceinline__ float gcg(const float* p) { return __ldcg(p); }

// product layer: out[m] = sum of 4 gathered log-probs.
// Two-wave grid-stride with 2-stage ptr pipeline: next iteration's ptr int4
// is in DRAM flight while this iteration's gathers (L2) are serviced; the
// second wave of blocks restores retirement-driven SM load rebalancing.
__global__ void __launch_bounds__(512) product_kernel(
        const float* __restrict__ src,
        const int4* __restrict__ ptrs,
        float* __restrict__ dst) {
    const int stride = gridDim.x * blockDim.x;
    int m = blockIdx.x * blockDim.x + threadIdx.x;
    if (m >= M_NODES) return;
    int4 p = __ldcs(ptrs + m);
    while (true) {
        int mn = m + stride;
        int4 pn;
        if (mn < M_NODES) pn = __ldcs(ptrs + mn);   // prefetch next ptrs
        float a = gcg(src + p.x);
        float b = gcg(src + p.y);
        float c = gcg(src + p.z);
        float d = gcg(src + p.w);
        __stcg(dst + m, (a + b) + (c + d));
        if (mn >= M_NODES) break;
        m = mn; p = pn;
    }
}

// sum layer: 4-way logsumexp with 1e-15 floor, max detached. Same pipeline.
__global__ void __launch_bounds__(512) sum_kernel(
        const float* __restrict__ src,
        const int4* __restrict__ ptrs,
        float* __restrict__ dst) {
    const int stride = gridDim.x * blockDim.x;
    int m = blockIdx.x * blockDim.x + threadIdx.x;
    if (m >= M_NODES) return;
    int4 p = __ldcs(ptrs + m);
    while (true) {
        int mn = m + stride;
        int4 pn;
        if (mn < M_NODES) pn = __ldcs(ptrs + mn);
        float a = gcg(src + p.x);
        float b = gcg(src + p.y);
        float c = gcg(src + p.z);
        float d = gcg(src + p.w);
        float mx = fmaxf(fmaxf(a, b), fmaxf(c, d));
        float out;
        if (mx == -INFINITY) {
            out = -INFINITY;            // reference nan_to_num path
        } else {
            float s = __expf(a - mx) + __expf(b - mx)
                    + __expf(c - mx) + __expf(d - mx);
            out = __logf(s + 1e-15f) + mx;
        }
        __stcg(dst + m, out);
        if (mn >= M_NODES) break;
        m = mn; p = pn;
    }
}

extern "C" void kernel_launch(void* const* d_in, const int* in_sizes, int n_in,
                              void* d_out, int out_size) {
    const float* pos   = (const float*)d_in[0];
    const int4*  ptrs0 = (const int4*)d_in[1];
    const int4*  ptrs1 = (const int4*)d_in[2];
    const int4*  ptrs2 = (const int4*)d_in[3];
    const int4*  ptrs3 = (const int4*)d_in[4];
    // d_in[5] (csr = repeat(arange(M),4)) is implicit in the layout.
    float* out = (float*)d_out;

    float* enc;  cudaGetSymbolAddress((void**)&enc,  g_enc);
    float* bufA; cudaGetSymbolAddress((void**)&bufA, g_bufA);
    float* bufB; cudaGetSymbolAddress((void**)&bufB, g_bufB);

    const int T = 512;
    const int blocksEnc = (N_IN + T - 1) / T;
    const int blocksM   = 148 * 8;   // two waves of 4-resident blocks/SM:
                                     // pipeline + retirement rebalancing

    encode_kernel <<<blocksEnc, T>>>(pos);
    product_kernel<<<blocksM, T>>>(enc,  ptrs0, bufA);
    sum_kernel    <<<blocksM, T>>>(bufA, ptrs1, bufB);
    product_kernel<<<blocksM, T>>>(bufB, ptrs2, bufA);
    sum_kernel    <<<blocksM, T>>>(bufA, ptrs3, out);
}